// round 1
// baseline (speedup 1.0000x reference)
#include <cuda_runtime.h>

#define B  32
#define S  617
#define D  10000
#define L  100
#define C  26
#define W  313        // ceil(D/32) real words
#define WP 320        // padded word count (divisible by 32 warps*? -> 40 blocks * 8 warps)
#define CH 8          // s-chunks
#define CLEN 78       // ceil(S/CH), divisible by 3
#define SP (CH*CLEN)  // 624 padded rows for id bits

// ---------------- scratch (device globals; zero-init at load, fully rewritten each launch) ----
__device__ int      g_idx[B * S];
__device__ unsigned g_idp[SP * WP];          // packed id signs  [s][w]
__device__ unsigned g_lvp[L * WP];           // packed level signs [l][w]
__device__ unsigned g_planes[B * CH * 7 * WP]; // per-(b,chunk) 7 bitplanes of disagree counts
__device__ unsigned g_enc[B * WP];           // packed enc bits (1 -> +1, 0 -> -1)

// ---------------- kernel 1: quantize x -> idx, pack id_weight & level_weight signs ------------
__global__ __launch_bounds__(256) void prep_kernel(const float* __restrict__ x,
                                                   const float* __restrict__ idw,
                                                   const float* __restrict__ lvw) {
    int warp = threadIdx.x >> 5;
    int lane = threadIdx.x & 31;
    int w    = blockIdx.x * 8 + warp;   // 0..319
    int row  = blockIdx.y;              // 0..S+L  (last slice = idx computation)

    if (row < S) {
        int d = w * 32 + lane;
        float v = (d < D) ? idw[row * D + d] : 0.0f;
        unsigned word = __ballot_sync(0xffffffffu, v > 0.0f);
        if (lane == 0) g_idp[row * WP + w] = word;
    } else if (row < S + L) {
        int l = row - S;
        int d = w * 32 + lane;
        float v = (d < D) ? lvw[l * D + d] : 0.0f;
        unsigned word = __ballot_sync(0xffffffffu, v > 0.0f);
        if (lane == 0) g_lvp[l * WP + w] = word;
    } else {
        // idx[b][s] = clip(rint(x*99), 0, 99)  (rintf = round-half-even, matches jnp.round)
        for (int i = blockIdx.x * 256 + threadIdx.x; i < B * S; i += 40 * 256) {
            int q = (int)rintf(x[i] * (float)(L - 1));
            q = min(max(q, 0), L - 1);
            g_idx[i] = q;
        }
    }
}

// ---------------- CSA: add three 1-bit vectors into 7 bitplanes --------------------------------
__device__ __forceinline__ void csa_add3(unsigned x0, unsigned x1, unsigned x2,
                                         unsigned& p0, unsigned& p1, unsigned& p2,
                                         unsigned& p3, unsigned& p4, unsigned& p5, unsigned& p6) {
    unsigned t  = x0 ^ x1;
    unsigned lo = t ^ x2;                       // XOR3 -> 1 LOP3
    unsigned hi = (x0 & x1) | (x2 & t);         // MAJ3 -> 1 LOP3
    unsigned c  = p0 & lo;  p0 ^= lo;           // HA at plane 0
    unsigned s1 = p1 ^ hi ^ c;                  // FA at plane 1 (hi + carry)
    unsigned c2 = (p1 & hi) | (c & (p1 ^ hi));
    p1 = s1; c = c2;
    t = p2 & c; p2 ^= c; c = t;                 // ripple (max count 78 < 128)
    t = p3 & c; p3 ^= c; c = t;
    t = p4 & c; p4 ^= c; c = t;
    t = p5 & c; p5 ^= c; c = t;
    p6 ^= c;
}

// ---------------- kernel 2: bind + count disagreements, bit-sliced -----------------------------
__global__ __launch_bounds__(WP) void main_kernel() {
    int b = blockIdx.x;
    int chunk = blockIdx.y;
    int s0 = chunk * CLEN;

    __shared__ int sidx[CLEN];
    if (threadIdx.x < CLEN) {
        int s = s0 + threadIdx.x;
        sidx[threadIdx.x] = (s < S) ? g_idx[b * S + s] : 0;
    }
    __syncthreads();

    int w = threadIdx.x;  // 0..319
    unsigned p0 = 0, p1 = 0, p2 = 0, p3 = 0, p4 = 0, p5 = 0, p6 = 0;
    const unsigned* idp = &g_idp[s0 * WP + w];

    if (s0 + CLEN <= S) {
        #pragma unroll
        for (int i = 0; i < CLEN; i += 3) {
            unsigned x0 = __ldg(idp + (i + 0) * WP) ^ __ldg(&g_lvp[sidx[i + 0] * WP + w]);
            unsigned x1 = __ldg(idp + (i + 1) * WP) ^ __ldg(&g_lvp[sidx[i + 1] * WP + w]);
            unsigned x2 = __ldg(idp + (i + 2) * WP) ^ __ldg(&g_lvp[sidx[i + 2] * WP + w]);
            csa_add3(x0, x1, x2, p0, p1, p2, p3, p4, p5, p6);
        }
    } else {
        #pragma unroll
        for (int i = 0; i < CLEN; i += 3) {
            unsigned x0 = (s0 + i + 0 < S) ? (__ldg(idp + (i + 0) * WP) ^ __ldg(&g_lvp[sidx[i + 0] * WP + w])) : 0u;
            unsigned x1 = (s0 + i + 1 < S) ? (__ldg(idp + (i + 1) * WP) ^ __ldg(&g_lvp[sidx[i + 1] * WP + w])) : 0u;
            unsigned x2 = (s0 + i + 2 < S) ? (__ldg(idp + (i + 2) * WP) ^ __ldg(&g_lvp[sidx[i + 2] * WP + w])) : 0u;
            csa_add3(x0, x1, x2, p0, p1, p2, p3, p4, p5, p6);
        }
    }

    unsigned base = (unsigned)(b * CH + chunk) * 7u * WP + (unsigned)w;
    g_planes[base + 0u * WP] = p0;
    g_planes[base + 1u * WP] = p1;
    g_planes[base + 2u * WP] = p2;
    g_planes[base + 3u * WP] = p3;
    g_planes[base + 4u * WP] = p4;
    g_planes[base + 5u * WP] = p5;
    g_planes[base + 6u * WP] = p6;
}

// ---------------- kernel 3: merge chunk bitplanes, bit-sliced compare cnt<309 -> packed enc ----
__global__ __launch_bounds__(WP) void enc_kernel() {
    int b = blockIdx.x;
    int w = threadIdx.x;

    unsigned A[10];
    #pragma unroll
    for (int k = 0; k < 10; k++) A[k] = 0u;

    const unsigned* pl = &g_planes[(unsigned)(b * CH) * 7u * WP + (unsigned)w];
    #pragma unroll
    for (int ch = 0; ch < CH; ch++) {
        unsigned c = 0u;
        #pragma unroll
        for (int k = 0; k < 7; k++) {
            unsigned q = pl[(ch * 7 + k) * WP];
            unsigned s = A[k] ^ q ^ c;
            c = (A[k] & q) | (c & (A[k] ^ q));
            A[k] = s;
        }
        #pragma unroll
        for (int k = 7; k < 10; k++) {
            unsigned t = A[k] & c; A[k] ^= c; c = t;
        }
    }

    // enc = +1  <=>  multiset = 617 - 2*cnt > 0  <=>  cnt <= 308  <=>  cnt < 309
    // 309 = 0b0100110101 ; MSB->LSB lexicographic compare, bit-sliced across 32 lanes.
    unsigned lt = 0u, eq = 0xffffffffu;
    eq &= ~A[9];                        // K9=0
    lt |= eq & ~A[8]; eq &= A[8];       // K8=1
    eq &= ~A[7];                        // K7=0
    eq &= ~A[6];                        // K6=0
    lt |= eq & ~A[5]; eq &= A[5];       // K5=1
    lt |= eq & ~A[4]; eq &= A[4];       // K4=1
    eq &= ~A[3];                        // K3=0
    lt |= eq & ~A[2]; eq &= A[2];       // K2=1
    eq &= ~A[1];                        // K1=0
    lt |= eq & ~A[0];                   // K0=1

    g_enc[b * WP + w] = lt;
}

// ---------------- kernel 4: logits = enc(+/-1) . classify^T ------------------------------------
__global__ __launch_bounds__(256) void logits_kernel(const float* __restrict__ cw,
                                                     float* __restrict__ out) {
    int c = blockIdx.x;

    float acc[B];
    #pragma unroll
    for (int b = 0; b < B; b++) acc[b] = 0.0f;

    for (int w = threadIdx.x; w < W; w += 256) {
        unsigned e[B];
        #pragma unroll
        for (int b = 0; b < B; b++) e[b] = g_enc[b * WP + w];
        int dbase = w * 32;
        int jmax = min(32, D - dbase);
        for (int j = 0; j < jmax; j++) {
            unsigned cb = __float_as_uint(__ldg(&cw[c * D + dbase + j]));
            #pragma unroll
            for (int b = 0; b < B; b++) {
                unsigned sgn = (~(e[b] >> j)) << 31;    // bit=1 -> +cls, bit=0 -> -cls
                acc[b] += __uint_as_float(cb ^ sgn);
            }
        }
    }

    __shared__ float red[8][B];
    int lane = threadIdx.x & 31;
    int warp = threadIdx.x >> 5;
    #pragma unroll
    for (int b = 0; b < B; b++) {
        float v = acc[b];
        #pragma unroll
        for (int o = 16; o > 0; o >>= 1) v += __shfl_down_sync(0xffffffffu, v, o);
        if (lane == 0) red[warp][b] = v;
    }
    __syncthreads();
    if (threadIdx.x < B) {
        float v = 0.0f;
        #pragma unroll
        for (int k = 0; k < 8; k++) v += red[k][threadIdx.x];
        out[threadIdx.x * C + c] = v;
    }
}

// ---------------- launch ------------------------------------------------------------------------
extern "C" void kernel_launch(void* const* d_in, const int* in_sizes, int n_in,
                              void* d_out, int out_size) {
    (void)in_sizes; (void)n_in; (void)out_size;
    const float* x   = (const float*)d_in[0];
    const float* idw = (const float*)d_in[1];
    const float* lvw = (const float*)d_in[2];
    const float* cw  = (const float*)d_in[3];
    float* out = (float*)d_out;

    prep_kernel<<<dim3(40, S + L + 1), 256>>>(x, idw, lvw);
    main_kernel<<<dim3(B, CH), WP>>>();
    enc_kernel<<<B, WP>>>();
    logits_kernel<<<C, 256>>>(cw, out);
}

// round 2
// speedup vs baseline: 1.1985x; 1.1985x over previous
#include <cuda_runtime.h>

#define B  32
#define S  617
#define D  10000
#define L  100
#define C  26
#define W  313        // ceil(D/32) real words
#define WP 320        // padded word count (even, uint2-friendly)
#define CH 8          // s-chunks
#define CLEN 78       // S/CH rounded up, divisible by 6

// ---------------- scratch (device globals; rewritten every launch where read) -------------------
__device__ __align__(16) int      g_idx[B * S];
__device__ __align__(16) unsigned g_idp[S * WP];             // packed id signs   [s][w]
__device__ __align__(16) unsigned g_lvp[L * WP];             // packed level signs [l][w]
__device__ __align__(16) unsigned g_planes[B * CH * 7 * WP]; // per-(b,chunk) 7 count bitplanes
__device__ __align__(16) unsigned g_enc[B * WP];             // packed enc (1 -> +1, 0 -> -1)

// ================= kernel 1: pack sign bits (float4 + shfl) and quantize x =====================
#define QR 79                      // ceil(D/128) float4-quads per row
#define NROWS (S + L)              // 717
#define PREP_BLOCKS 592

__global__ __launch_bounds__(256) void prep_kernel(const float* __restrict__ x,
                                                   const float* __restrict__ idw,
                                                   const float* __restrict__ lvw) {
    const int lane = threadIdx.x & 31;
    const int wrp  = (blockIdx.x * 256 + threadIdx.x) >> 5;     // 0..4735
    const int NW   = PREP_BLOCKS * 8;                           // 4736 warps
    const int NTASK = NROWS * QR;

    for (int task = wrp; task < NTASK; task += NW) {
        int r = task / QR;
        int q = task - r * QR;
        const float* src = (r < S) ? (idw + (size_t)r * D) : (lvw + (size_t)(r - S) * D);
        unsigned*    dst = (r < S) ? (g_idp + r * WP)       : (g_lvp + (r - S) * WP);

        int d0 = q * 128 + lane * 4;
        unsigned nib = 0u;
        if (d0 + 3 < D) {
            float4 v = *reinterpret_cast<const float4*>(src + d0);
            nib  = (v.x > 0.0f) ? 1u : 0u;
            nib |= (v.y > 0.0f) ? 2u : 0u;
            nib |= (v.z > 0.0f) ? 4u : 0u;
            nib |= (v.w > 0.0f) ? 8u : 0u;
        } else if (d0 < D) {
            #pragma unroll
            for (int k = 0; k < 4; k++)
                if (d0 + k < D && src[d0 + k] > 0.0f) nib |= (1u << k);
        }
        // pack 8 nibbles -> one 32-bit word on lanes 0,8,16,24 (bit order == d order)
        unsigned xv = nib;
        xv |= __shfl_down_sync(0xffffffffu, xv, 1) << 4;
        xv |= __shfl_down_sync(0xffffffffu, xv, 2) << 8;
        xv |= __shfl_down_sync(0xffffffffu, xv, 4) << 16;
        if ((lane & 7) == 0) {
            int w = q * 4 + (lane >> 3);
            if (w < WP) dst[w] = xv;
        }
    }

    // quantize x -> level idx (rintf == round-half-even, matches jnp.round)
    int gt = blockIdx.x * 256 + threadIdx.x;
    if (gt < B * S) {
        int qv = (int)rintf(x[gt] * (float)(L - 1));
        g_idx[gt] = min(max(qv, 0), L - 1);
    }
}

// ================= 6-sample bitplane compressor (26 LOP3 per 6 samples) =========================
__device__ __forceinline__ void csa6(const unsigned xx[6], unsigned p[7]) {
    unsigned t01 = xx[0] ^ xx[1];
    unsigned l1  = t01 ^ xx[2];
    unsigned h1  = (xx[0] & xx[1]) | (xx[2] & t01);
    unsigned t34 = xx[3] ^ xx[4];
    unsigned l2  = t34 ^ xx[5];
    unsigned h2  = (xx[3] & xx[4]) | (xx[5] & t34);
    // plane0: FA(p0, l1, l2)
    unsigned tl = l1 ^ l2;
    unsigned c0 = (l1 & l2) | (p[0] & tl);
    p[0] ^= tl;
    // plane1: FA(p1, h1, h2) then HA(+c0) -> two carries into plane2
    unsigned th  = h1 ^ h2;
    unsigned c1a = (h1 & h2) | (p[1] & th);
    unsigned s1  = p[1] ^ th;
    unsigned c1b = s1 & c0;
    p[1] = s1 ^ c0;
    // plane2: FA(p2, c1a, c1b)
    unsigned tc = c1a ^ c1b;
    unsigned c2 = (c1a & c1b) | (p[2] & tc);
    p[2] ^= tc;
    // ripple single carry up
    unsigned t;
    t = p[3] & c2; p[3] ^= c2; c2 = t;
    t = p[4] & c2; p[4] ^= c2; c2 = t;
    t = p[5] & c2; p[5] ^= c2; c2 = t;
    p[6] ^= c2;
}

// ================= kernel 2: bind + bit-sliced disagreement count (uint2 = 2 words/thread) =====
__global__ __launch_bounds__(160) void main_kernel() {
    const int b     = blockIdx.x;
    const int chunk = blockIdx.y;
    const int s0    = chunk * CLEN;

    __shared__ int sidx[CLEN];
    if (threadIdx.x < CLEN) {
        int s = s0 + threadIdx.x;
        sidx[threadIdx.x] = (s < S) ? g_idx[b * S + s] : 0;
    }
    __syncthreads();

    const int t = threadIdx.x;       // word-pair index: words 2t, 2t+1
    unsigned pA[7] = {0,0,0,0,0,0,0};
    unsigned pB[7] = {0,0,0,0,0,0,0};
    const uint2* idp = reinterpret_cast<const uint2*>(g_idp + s0 * WP) + t;

    if (s0 + CLEN <= S) {
        for (int g = 0; g < CLEN / 6; g++) {
            unsigned xa[6], xb[6];
            #pragma unroll
            for (int k = 0; k < 6; k++) {
                int i = g * 6 + k;
                uint2 a = idp[i * (WP / 2)];
                uint2 l = *(reinterpret_cast<const uint2*>(g_lvp + sidx[i] * WP) + t);
                xa[k] = a.x ^ l.x;
                xb[k] = a.y ^ l.y;
            }
            csa6(xa, pA);
            csa6(xb, pB);
        }
    } else {
        for (int g = 0; g < CLEN / 6; g++) {
            unsigned xa[6], xb[6];
            #pragma unroll
            for (int k = 0; k < 6; k++) {
                int i = g * 6 + k;
                if (s0 + i < S) {
                    uint2 a = idp[i * (WP / 2)];
                    uint2 l = *(reinterpret_cast<const uint2*>(g_lvp + sidx[i] * WP) + t);
                    xa[k] = a.x ^ l.x;
                    xb[k] = a.y ^ l.y;
                } else {
                    xa[k] = 0u; xb[k] = 0u;
                }
            }
            csa6(xa, pA);
            csa6(xb, pB);
        }
    }

    unsigned* base = g_planes + (b * CH + chunk) * 7 * WP;
    #pragma unroll
    for (int k = 0; k < 7; k++) {
        uint2 v; v.x = pA[k]; v.y = pB[k];
        *(reinterpret_cast<uint2*>(base + k * WP) + t) = v;
    }
}

// ================= bit-sliced compare cnt < 309 (309 = 0b0100110101) ===========================
__device__ __forceinline__ unsigned cmp309(const unsigned A[10]) {
    unsigned lt = 0u, eq = 0xffffffffu;
    eq &= ~A[9];                        // K9=0
    lt |= eq & ~A[8]; eq &= A[8];       // K8=1
    eq &= ~A[7];                        // K7=0
    eq &= ~A[6];                        // K6=0
    lt |= eq & ~A[5]; eq &= A[5];       // K5=1
    lt |= eq & ~A[4]; eq &= A[4];       // K4=1
    eq &= ~A[3];                        // K3=0
    lt |= eq & ~A[2]; eq &= A[2];       // K2=1
    eq &= ~A[1];                        // K1=0
    lt |= eq & ~A[0];                   // K0=1
    return lt;
}

// ================= kernel 3: merge chunk bitplanes -> packed enc ================================
__global__ __launch_bounds__(160) void enc_kernel() {
    const int b = blockIdx.x;
    const int t = threadIdx.x;

    unsigned A[10], Bv[10];
    #pragma unroll
    for (int k = 0; k < 10; k++) { A[k] = 0u; Bv[k] = 0u; }

    const unsigned* pl = g_planes + b * CH * 7 * WP;
    #pragma unroll
    for (int ch = 0; ch < CH; ch++) {
        unsigned cA = 0u, cB = 0u;
        #pragma unroll
        for (int k = 0; k < 7; k++) {
            uint2 q = *(reinterpret_cast<const uint2*>(pl + (ch * 7 + k) * WP) + t);
            unsigned sA = A[k] ^ q.x ^ cA;
            cA = (A[k] & q.x) | (cA & (A[k] ^ q.x));
            A[k] = sA;
            unsigned sB = Bv[k] ^ q.y ^ cB;
            cB = (Bv[k] & q.y) | (cB & (Bv[k] ^ q.y));
            Bv[k] = sB;
        }
        #pragma unroll
        for (int k = 7; k < 10; k++) {
            unsigned tA = A[k] & cA;  A[k] ^= cA;  cA = tA;
            unsigned tB = Bv[k] & cB; Bv[k] ^= cB; cB = tB;
        }
    }

    uint2 v; v.x = cmp309(A); v.y = cmp309(Bv);
    *(reinterpret_cast<uint2*>(g_enc + b * WP) + t) = v;
}

// ================= kernel 4: logits = enc(+/-1) . classify^T (lanes = j, coalesced) =============
__global__ __launch_bounds__(320) void logits_kernel(const float* __restrict__ cw,
                                                     float* __restrict__ out) {
    const int c    = blockIdx.x;
    const int bg   = blockIdx.y * 8;
    const int lane = threadIdx.x & 31;
    const int wrp  = threadIdx.x >> 5;   // 0..9

    float acc[8];
    #pragma unroll
    for (int i = 0; i < 8; i++) acc[i] = 0.0f;

    for (int w = wrp; w < W; w += 10) {
        int d = w * 32 + lane;
        float cb = (d < D) ? __ldg(&cw[c * D + d]) : 0.0f;
        unsigned cbu = __float_as_uint(cb);
        #pragma unroll
        for (int i = 0; i < 8; i++) {
            unsigned e   = g_enc[(bg + i) * WP + w];          // uniform -> broadcast
            unsigned sgn = (~(e >> lane)) << 31;              // bit=1 -> +, bit=0 -> -
            acc[i] += __uint_as_float(cbu ^ sgn);
        }
    }

    __shared__ float red[10][8];
    #pragma unroll
    for (int i = 0; i < 8; i++) {
        float v = acc[i];
        #pragma unroll
        for (int o = 16; o > 0; o >>= 1) v += __shfl_down_sync(0xffffffffu, v, o);
        if (lane == 0) red[wrp][i] = v;
    }
    __syncthreads();
    if (threadIdx.x < 8) {
        float v = 0.0f;
        #pragma unroll
        for (int k = 0; k < 10; k++) v += red[k][threadIdx.x];
        out[(bg + threadIdx.x) * C + c] = v;
    }
}

// ================= launch =======================================================================
extern "C" void kernel_launch(void* const* d_in, const int* in_sizes, int n_in,
                              void* d_out, int out_size) {
    (void)in_sizes; (void)n_in; (void)out_size;
    const float* x   = (const float*)d_in[0];
    const float* idw = (const float*)d_in[1];
    const float* lvw = (const float*)d_in[2];
    const float* cw  = (const float*)d_in[3];
    float* out = (float*)d_out;

    prep_kernel<<<PREP_BLOCKS, 256>>>(x, idw, lvw);
    main_kernel<<<dim3(B, CH), 160>>>();
    enc_kernel<<<B, 160>>>();
    logits_kernel<<<dim3(C, 4), 320>>>(cw, out);
}

// round 3
// speedup vs baseline: 1.3969x; 1.1656x over previous
#include <cuda_runtime.h>

#define B  32
#define S  617
#define D  10000
#define L  100
#define C  26
#define W  313        // ceil(D/32) real words
#define WP 320        // padded word count (even, uint2-friendly)
#define CH 8          // s-chunks
#define CLEN 78       // S/CH rounded up, divisible by 6

// ---------------- scratch (device globals; rewritten every launch where read) -------------------
__device__ __align__(16) int      g_idx[B * S];
__device__ __align__(16) unsigned g_idp[S * WP];             // packed id signs   [s][w]
__device__ __align__(16) unsigned g_lvp[L * WP];             // packed level signs [l][w]
__device__ __align__(16) unsigned g_planes[B * CH * 7 * WP]; // per-(b,chunk) 7 count bitplanes
__device__ __align__(16) unsigned g_enc[B * WP];             // packed enc (1 -> +1, 0 -> -1)

// ================= kernel 1: pack sign bits (float4 + shfl) and quantize x =====================
#define QR 79                      // ceil(D/128) float4-quads per row
#define NROWS (S + L)              // 717
#define PREP_BLOCKS 592

__global__ __launch_bounds__(256) void prep_kernel(const float* __restrict__ x,
                                                   const float* __restrict__ idw,
                                                   const float* __restrict__ lvw) {
    const int lane = threadIdx.x & 31;
    const int wrp  = (blockIdx.x * 256 + threadIdx.x) >> 5;     // 0..4735
    const int NW   = PREP_BLOCKS * 8;                           // 4736 warps
    const int NTASK = NROWS * QR;

    for (int task = wrp; task < NTASK; task += NW) {
        int r = task / QR;
        int q = task - r * QR;
        const float* src = (r < S) ? (idw + (size_t)r * D) : (lvw + (size_t)(r - S) * D);
        unsigned*    dst = (r < S) ? (g_idp + r * WP)       : (g_lvp + (r - S) * WP);

        int d0 = q * 128 + lane * 4;
        unsigned nib = 0u;
        if (d0 + 3 < D) {
            float4 v = *reinterpret_cast<const float4*>(src + d0);
            nib  = (v.x > 0.0f) ? 1u : 0u;
            nib |= (v.y > 0.0f) ? 2u : 0u;
            nib |= (v.z > 0.0f) ? 4u : 0u;
            nib |= (v.w > 0.0f) ? 8u : 0u;
        } else if (d0 < D) {
            #pragma unroll
            for (int k = 0; k < 4; k++)
                if (d0 + k < D && src[d0 + k] > 0.0f) nib |= (1u << k);
        }
        // pack 8 nibbles -> one 32-bit word on lanes 0,8,16,24 (bit order == d order)
        unsigned xv = nib;
        xv |= __shfl_down_sync(0xffffffffu, xv, 1) << 4;
        xv |= __shfl_down_sync(0xffffffffu, xv, 2) << 8;
        xv |= __shfl_down_sync(0xffffffffu, xv, 4) << 16;
        if ((lane & 7) == 0) {
            int w = q * 4 + (lane >> 3);
            if (w < WP) dst[w] = xv;
        }
    }

    // quantize x -> level idx (rintf == round-half-even, matches jnp.round)
    int gt = blockIdx.x * 256 + threadIdx.x;
    if (gt < B * S) {
        int qv = (int)rintf(x[gt] * (float)(L - 1));
        g_idx[gt] = min(max(qv, 0), L - 1);
    }
}

// ================= 6-sample bitplane compressor (26 LOP3 per 6 samples) =========================
__device__ __forceinline__ void csa6(const unsigned xx[6], unsigned p[7]) {
    unsigned t01 = xx[0] ^ xx[1];
    unsigned l1  = t01 ^ xx[2];
    unsigned h1  = (xx[0] & xx[1]) | (xx[2] & t01);
    unsigned t34 = xx[3] ^ xx[4];
    unsigned l2  = t34 ^ xx[5];
    unsigned h2  = (xx[3] & xx[4]) | (xx[5] & t34);
    // plane0: FA(p0, l1, l2)
    unsigned tl = l1 ^ l2;
    unsigned c0 = (l1 & l2) | (p[0] & tl);
    p[0] ^= tl;
    // plane1: FA(p1, h1, h2) then HA(+c0) -> two carries into plane2
    unsigned th  = h1 ^ h2;
    unsigned c1a = (h1 & h2) | (p[1] & th);
    unsigned s1  = p[1] ^ th;
    unsigned c1b = s1 & c0;
    p[1] = s1 ^ c0;
    // plane2: FA(p2, c1a, c1b)
    unsigned tc = c1a ^ c1b;
    unsigned c2 = (c1a & c1b) | (p[2] & tc);
    p[2] ^= tc;
    // ripple single carry up
    unsigned t;
    t = p[3] & c2; p[3] ^= c2; c2 = t;
    t = p[4] & c2; p[4] ^= c2; c2 = t;
    t = p[5] & c2; p[5] ^= c2; c2 = t;
    p[6] ^= c2;
}

// ================= kernel 2: bind + bit-sliced disagreement count (uint2 = 2 words/thread) =====
__global__ __launch_bounds__(160) void main_kernel() {
    const int b     = blockIdx.x;
    const int chunk = blockIdx.y;
    const int s0    = chunk * CLEN;

    __shared__ int sidx[CLEN];
    if (threadIdx.x < CLEN) {
        int s = s0 + threadIdx.x;
        sidx[threadIdx.x] = (s < S) ? g_idx[b * S + s] : 0;
    }
    __syncthreads();

    const int t = threadIdx.x;       // word-pair index: words 2t, 2t+1
    unsigned pA[7] = {0,0,0,0,0,0,0};
    unsigned pB[7] = {0,0,0,0,0,0,0};
    const uint2* idp = reinterpret_cast<const uint2*>(g_idp + s0 * WP) + t;

    if (s0 + CLEN <= S) {
        for (int g = 0; g < CLEN / 6; g++) {
            unsigned xa[6], xb[6];
            #pragma unroll
            for (int k = 0; k < 6; k++) {
                int i = g * 6 + k;
                uint2 a = idp[i * (WP / 2)];
                uint2 l = *(reinterpret_cast<const uint2*>(g_lvp + sidx[i] * WP) + t);
                xa[k] = a.x ^ l.x;
                xb[k] = a.y ^ l.y;
            }
            csa6(xa, pA);
            csa6(xb, pB);
        }
    } else {
        for (int g = 0; g < CLEN / 6; g++) {
            unsigned xa[6], xb[6];
            #pragma unroll
            for (int k = 0; k < 6; k++) {
                int i = g * 6 + k;
                if (s0 + i < S) {
                    uint2 a = idp[i * (WP / 2)];
                    uint2 l = *(reinterpret_cast<const uint2*>(g_lvp + sidx[i] * WP) + t);
                    xa[k] = a.x ^ l.x;
                    xb[k] = a.y ^ l.y;
                } else {
                    xa[k] = 0u; xb[k] = 0u;
                }
            }
            csa6(xa, pA);
            csa6(xb, pB);
        }
    }

    unsigned* base = g_planes + (b * CH + chunk) * 7 * WP;
    #pragma unroll
    for (int k = 0; k < 7; k++) {
        uint2 v; v.x = pA[k]; v.y = pB[k];
        *(reinterpret_cast<uint2*>(base + k * WP) + t) = v;
    }
}

// ================= bit-sliced compare cnt < 309 (309 = 0b0100110101) ===========================
__device__ __forceinline__ unsigned cmp309(const unsigned A[10]) {
    unsigned lt = 0u, eq = 0xffffffffu;
    eq &= ~A[9];                        // K9=0
    lt |= eq & ~A[8]; eq &= A[8];       // K8=1
    eq &= ~A[7];                        // K7=0
    eq &= ~A[6];                        // K6=0
    lt |= eq & ~A[5]; eq &= A[5];       // K5=1
    lt |= eq & ~A[4]; eq &= A[4];       // K4=1
    eq &= ~A[3];                        // K3=0
    lt |= eq & ~A[2]; eq &= A[2];       // K2=1
    eq &= ~A[1];                        // K1=0
    lt |= eq & ~A[0];                   // K0=1
    return lt;
}

// ================= kernel 3: merge chunk bitplanes -> packed enc ================================
__global__ __launch_bounds__(160) void enc_kernel() {
    const int b = blockIdx.x;
    const int t = threadIdx.x;

    unsigned A[10], Bv[10];
    #pragma unroll
    for (int k = 0; k < 10; k++) { A[k] = 0u; Bv[k] = 0u; }

    const unsigned* pl = g_planes + b * CH * 7 * WP;
    #pragma unroll
    for (int ch = 0; ch < CH; ch++) {
        unsigned cA = 0u, cB = 0u;
        #pragma unroll
        for (int k = 0; k < 7; k++) {
            uint2 q = *(reinterpret_cast<const uint2*>(pl + (ch * 7 + k) * WP) + t);
            unsigned sA = A[k] ^ q.x ^ cA;
            cA = (A[k] & q.x) | (cA & (A[k] ^ q.x));
            A[k] = sA;
            unsigned sB = Bv[k] ^ q.y ^ cB;
            cB = (Bv[k] & q.y) | (cB & (Bv[k] ^ q.y));
            Bv[k] = sB;
        }
        #pragma unroll
        for (int k = 7; k < 10; k++) {
            unsigned tA = A[k] & cA;  A[k] ^= cA;  cA = tA;
            unsigned tB = Bv[k] & cB; Bv[k] ^= cB; cB = tB;
        }
    }

    uint2 v; v.x = cmp309(A); v.y = cmp309(Bv);
    *(reinterpret_cast<uint2*>(g_enc + b * WP) + t) = v;
}

// ================= kernel 4: logits = enc(+/-1) . classify^T ===================================
// grid (C, B/4), 320 threads. 4 batches per block; enc rows staged in smem.
// Thread handles d = k*320 + tid  ->  enc word index (d>>5) is UNIFORM per warp (= k*10 + warp),
// bit index = lane. 1 coalesced LDG + 4 broadcast LDS + 4 LOP3+FADD per iteration.
__global__ __launch_bounds__(320) void logits_kernel(const float* __restrict__ cw,
                                                     float* __restrict__ out) {
    const int c    = blockIdx.x;
    const int b0   = blockIdx.y * 4;
    const int tid  = threadIdx.x;
    const int lane = tid & 31;
    const int wrp  = tid >> 5;   // 0..9

    __shared__ unsigned se[4 * WP];
    #pragma unroll
    for (int i = 0; i < 4; i++)
        se[i * WP + tid] = g_enc[(b0 + i) * WP + tid];
    __syncthreads();

    const float* cwc = cw + (size_t)c * D;

    float acc0 = 0.0f, acc1 = 0.0f, acc2 = 0.0f, acc3 = 0.0f;

    #pragma unroll 4
    for (int k = 0; k < 32; k++) {
        int d = k * 320 + tid;
        if (d < D) {
            unsigned cb = __float_as_uint(__ldg(cwc + d));
            int w = k * 10 + wrp;   // == d >> 5, uniform per warp
            unsigned e0 = se[0 * WP + w];
            unsigned e1 = se[1 * WP + w];
            unsigned e2 = se[2 * WP + w];
            unsigned e3 = se[3 * WP + w];
            // bit=1 -> +cb, bit=0 -> -cb  (flip sign bit)
            acc0 += __uint_as_float(cb ^ ((~(e0 >> lane)) << 31));
            acc1 += __uint_as_float(cb ^ ((~(e1 >> lane)) << 31));
            acc2 += __uint_as_float(cb ^ ((~(e2 >> lane)) << 31));
            acc3 += __uint_as_float(cb ^ ((~(e3 >> lane)) << 31));
        }
    }

    __shared__ float red[10][4];
    float a[4] = {acc0, acc1, acc2, acc3};
    #pragma unroll
    for (int i = 0; i < 4; i++) {
        float v = a[i];
        #pragma unroll
        for (int o = 16; o > 0; o >>= 1) v += __shfl_down_sync(0xffffffffu, v, o);
        if (lane == 0) red[wrp][i] = v;
    }
    __syncthreads();
    if (tid < 4) {
        float v = 0.0f;
        #pragma unroll
        for (int k = 0; k < 10; k++) v += red[k][tid];
        out[(b0 + tid) * C + c] = v;
    }
}

// ================= launch =======================================================================
extern "C" void kernel_launch(void* const* d_in, const int* in_sizes, int n_in,
                              void* d_out, int out_size) {
    (void)in_sizes; (void)n_in; (void)out_size;
    const float* x   = (const float*)d_in[0];
    const float* idw = (const float*)d_in[1];
    const float* lvw = (const float*)d_in[2];
    const float* cw  = (const float*)d_in[3];
    float* out = (float*)d_out;

    prep_kernel<<<PREP_BLOCKS, 256>>>(x, idw, lvw);
    main_kernel<<<dim3(B, CH), 160>>>();
    enc_kernel<<<B, 160>>>();
    logits_kernel<<<dim3(C, B / 4), 320>>>(cw, out);
}

// round 4
// speedup vs baseline: 2.1231x; 1.5198x over previous
#include <cuda_runtime.h>

#define B  32
#define S  617
#define D  10000
#define L  100
#define C  26
#define W  313        // ceil(D/32) real words
#define WP 320        // padded word count

// ---------------- scratch (device globals) ------------------------------------------------------
__device__ __align__(16) int      g_idx[B * S];
__device__ __align__(16) unsigned g_idp[S * WP];   // packed id signs    [s][w]  (w>=316 stay 0)
__device__ __align__(16) unsigned g_lvp[L * WP];   // packed level signs [l][w]
__device__ __align__(16) unsigned g_enc[B * WP];   // packed enc (1 -> +1, 0 -> -1)

// ================= kernel 1: pack sign bits (float4 + shfl) and quantize x =====================
#define QR 79                      // ceil(D/128) float4-quads per row
#define NROWS (S + L)              // 717
#define PREP_BLOCKS 592

__global__ __launch_bounds__(256) void prep_kernel(const float* __restrict__ x,
                                                   const float* __restrict__ idw,
                                                   const float* __restrict__ lvw) {
    const int lane = threadIdx.x & 31;
    const int wrp  = (blockIdx.x * 256 + threadIdx.x) >> 5;     // 0..4735
    const int NW   = PREP_BLOCKS * 8;
    const int NTASK = NROWS * QR;

    for (int task = wrp; task < NTASK; task += NW) {
        int r = task / QR;
        int q = task - r * QR;
        const float* src = (r < S) ? (idw + (size_t)r * D) : (lvw + (size_t)(r - S) * D);
        unsigned*    dst = (r < S) ? (g_idp + r * WP)       : (g_lvp + (r - S) * WP);

        int d0 = q * 128 + lane * 4;
        unsigned nib = 0u;
        if (d0 + 3 < D) {
            float4 v = *reinterpret_cast<const float4*>(src + d0);
            nib  = (v.x > 0.0f) ? 1u : 0u;
            nib |= (v.y > 0.0f) ? 2u : 0u;
            nib |= (v.z > 0.0f) ? 4u : 0u;
            nib |= (v.w > 0.0f) ? 8u : 0u;
        } else if (d0 < D) {
            #pragma unroll
            for (int k = 0; k < 4; k++)
                if (d0 + k < D && src[d0 + k] > 0.0f) nib |= (1u << k);
        }
        unsigned xv = nib;
        xv |= __shfl_down_sync(0xffffffffu, xv, 1) << 4;
        xv |= __shfl_down_sync(0xffffffffu, xv, 2) << 8;
        xv |= __shfl_down_sync(0xffffffffu, xv, 4) << 16;
        if ((lane & 7) == 0) {
            int w = q * 4 + (lane >> 3);
            if (w < WP) dst[w] = xv;
        }
    }

    int gt = blockIdx.x * 256 + threadIdx.x;
    if (gt < B * S) {
        int qv = (int)rintf(x[gt] * (float)(L - 1));   // round-half-even == jnp.round
        g_idx[gt] = min(max(qv, 0), L - 1);
    }
}

// ================= 6-sample bitplane compressor (26 LOP3 per 6 samples) =========================
__device__ __forceinline__ void csa6(const unsigned xx[6], unsigned p[7]) {
    unsigned t01 = xx[0] ^ xx[1];
    unsigned l1  = t01 ^ xx[2];
    unsigned h1  = (xx[0] & xx[1]) | (xx[2] & t01);
    unsigned t34 = xx[3] ^ xx[4];
    unsigned l2  = t34 ^ xx[5];
    unsigned h2  = (xx[3] & xx[4]) | (xx[5] & t34);
    unsigned tl = l1 ^ l2;
    unsigned c0 = (l1 & l2) | (p[0] & tl);
    p[0] ^= tl;
    unsigned th  = h1 ^ h2;
    unsigned c1a = (h1 & h2) | (p[1] & th);
    unsigned s1  = p[1] ^ th;
    unsigned c1b = s1 & c0;
    p[1] = s1 ^ c0;
    unsigned tc = c1a ^ c1b;
    unsigned c2 = (c1a & c1b) | (p[2] & tc);
    p[2] ^= tc;
    unsigned t;
    t = p[3] & c2; p[3] ^= c2; c2 = t;
    t = p[4] & c2; p[4] ^= c2; c2 = t;
    t = p[5] & c2; p[5] ^= c2; c2 = t;
    p[6] ^= c2;
}

// ================= bit-sliced compare cnt < 309 (309 = 0b0100110101) ===========================
__device__ __forceinline__ unsigned cmp309(const unsigned A[10]) {
    unsigned lt = 0u, eq = 0xffffffffu;
    eq &= ~A[9];
    lt |= eq & ~A[8]; eq &= A[8];
    eq &= ~A[7];
    eq &= ~A[6];
    lt |= eq & ~A[5]; eq &= A[5];
    lt |= eq & ~A[4]; eq &= A[4];
    eq &= ~A[3];
    lt |= eq & ~A[2]; eq &= A[2];
    eq &= ~A[1];
    lt |= eq & ~A[0];
    return lt;
}

// ================= kernel 2 (fused): bind + count + merge + quantize -> g_enc ===================
// grid (B, 10), 320 threads = 10 s-group warps x 32 words. Planes merged in smem; warp 0
// finishes with the 10-bit accumulate + cmp309. No g_planes round-trip, no enc kernel.
__global__ __launch_bounds__(320) void main_kernel() {
    const int b  = blockIdx.x;
    const int wg = blockIdx.y;             // 0..9 word group
    const int sg = threadIdx.x >> 5;       // 0..9 sample group (warp)
    const int wl = threadIdx.x & 31;
    const int w  = wg * 32 + wl;           // word 0..319

    __shared__ int      sidx[S];
    __shared__ unsigned pl[7 * 320];

    for (int s = threadIdx.x; s < S; s += 320) sidx[s] = g_idx[b * S + s];
    __syncthreads();

    const int s0 = sg * 62;
    const int sn = (sg == 9) ? 59 : 62;    // 9*62 + 59 = 617

    unsigned p[7] = {0, 0, 0, 0, 0, 0, 0};

    const int full6 = sn / 6;              // 10 or 9
    for (int g = 0; g < full6; g++) {
        unsigned xx[6];
        #pragma unroll
        for (int k = 0; k < 6; k++) {
            int s = s0 + g * 6 + k;
            xx[k] = __ldg(&g_idp[s * WP + w]) ^ __ldg(&g_lvp[sidx[s] * WP + w]);
        }
        csa6(xx, p);
    }
    for (int s = s0 + full6 * 6; s < s0 + sn; s++) {   // remainder: 2 or 5 samples
        unsigned c = __ldg(&g_idp[s * WP + w]) ^ __ldg(&g_lvp[sidx[s] * WP + w]);
        #pragma unroll
        for (int k = 0; k < 7; k++) { unsigned t = p[k] & c; p[k] ^= c; c = t; }
    }

    #pragma unroll
    for (int k = 0; k < 7; k++) pl[k * 320 + threadIdx.x] = p[k];
    __syncthreads();

    if (threadIdx.x < 32) {
        unsigned A[10];
        #pragma unroll
        for (int k = 0; k < 10; k++) A[k] = 0u;
        #pragma unroll
        for (int g2 = 0; g2 < 10; g2++) {
            unsigned c = 0u;
            #pragma unroll
            for (int k = 0; k < 7; k++) {
                unsigned q = pl[k * 320 + g2 * 32 + wl];
                unsigned s2 = A[k] ^ q ^ c;
                c = (A[k] & q) | (c & (A[k] ^ q));
                A[k] = s2;
            }
            #pragma unroll
            for (int k = 7; k < 10; k++) { unsigned t = A[k] & c; A[k] ^= c; c = t; }
        }
        g_enc[b * WP + wg * 32 + wl] = cmp309(A);
    }
}

// ================= kernel 3: logits = enc(+/-1) . classify^T ===================================
// grid (C, B/4), 320 threads. enc for the 4 batches packed as uint4 per word in smem
// (1 broadcast LDS.128/iter). 31 branch-free fully-unrolled iterations + 80-thread tail.
// sign apply: u = e << (31-lane); val = cb ^ (~u & 0x80000000)  -> SHF + 1 LOP3 + FADD.
__global__ __launch_bounds__(320) void logits_kernel(const float* __restrict__ cw,
                                                     float* __restrict__ out) {
    const int c    = blockIdx.x;
    const int b0   = blockIdx.y * 4;
    const int tid  = threadIdx.x;
    const int lane = tid & 31;
    const int wrp  = tid >> 5;            // 0..9
    const int sh   = 31 - lane;

    __shared__ uint4 se4[WP];
    {
        uint4 v;
        v.x = g_enc[(b0 + 0) * WP + tid];
        v.y = g_enc[(b0 + 1) * WP + tid];
        v.z = g_enc[(b0 + 2) * WP + tid];
        v.w = g_enc[(b0 + 3) * WP + tid];
        se4[tid] = v;
    }
    __syncthreads();

    const float* cwc = cw + (size_t)c * D;
    const unsigned MSB = 0x80000000u;

    float a0 = 0.0f, a1 = 0.0f, a2 = 0.0f, a3 = 0.0f;

    #pragma unroll
    for (int k = 0; k < 31; k++) {
        int d = k * 320 + tid;                       // max 9919 < D, no guard
        unsigned cb = __float_as_uint(__ldg(cwc + d));
        uint4 e = se4[k * 10 + wrp];                 // uniform per warp -> broadcast
        a0 += __uint_as_float(cb ^ (~(e.x << sh) & MSB));
        a1 += __uint_as_float(cb ^ (~(e.y << sh) & MSB));
        a2 += __uint_as_float(cb ^ (~(e.z << sh) & MSB));
        a3 += __uint_as_float(cb ^ (~(e.w << sh) & MSB));
    }
    if (tid < 80) {                                  // tail: d = 9920..9999, wrp <= 2
        int d = 9920 + tid;
        unsigned cb = __float_as_uint(__ldg(cwc + d));
        uint4 e = se4[310 + wrp];
        a0 += __uint_as_float(cb ^ (~(e.x << sh) & MSB));
        a1 += __uint_as_float(cb ^ (~(e.y << sh) & MSB));
        a2 += __uint_as_float(cb ^ (~(e.z << sh) & MSB));
        a3 += __uint_as_float(cb ^ (~(e.w << sh) & MSB));
    }

    __shared__ float red[10][4];
    float a[4] = {a0, a1, a2, a3};
    #pragma unroll
    for (int i = 0; i < 4; i++) {
        float v = a[i];
        #pragma unroll
        for (int o = 16; o > 0; o >>= 1) v += __shfl_down_sync(0xffffffffu, v, o);
        if (lane == 0) red[wrp][i] = v;
    }
    __syncthreads();
    if (tid < 4) {
        float v = 0.0f;
        #pragma unroll
        for (int k = 0; k < 10; k++) v += red[k][tid];
        out[(b0 + tid) * C + c] = v;
    }
}

// ================= launch =======================================================================
extern "C" void kernel_launch(void* const* d_in, const int* in_sizes, int n_in,
                              void* d_out, int out_size) {
    (void)in_sizes; (void)n_in; (void)out_size;
    const float* x   = (const float*)d_in[0];
    const float* idw = (const float*)d_in[1];
    const float* lvw = (const float*)d_in[2];
    const float* cw  = (const float*)d_in[3];
    float* out = (float*)d_out;

    prep_kernel<<<PREP_BLOCKS, 256>>>(x, idw, lvw);
    main_kernel<<<dim3(B, 10), 320>>>();
    logits_kernel<<<dim3(C, B / 4), 320>>>(cw, out);
}

// round 5
// speedup vs baseline: 2.3695x; 1.1160x over previous
#include <cuda_runtime.h>

#define B  32
#define S  617
#define D  10000
#define L  100
#define C  26
#define W  313        // ceil(D/32) real words
#define WP 320        // padded word count

// ---------------- scratch (device globals) ------------------------------------------------------
__device__ __align__(16) int      g_idx[B * S];
__device__ __align__(16) unsigned g_idp[S * WP];   // packed id signs    [s][w]  (w>=313 stay 0)
__device__ __align__(16) unsigned g_lvp[L * WP];   // packed level signs [l][w]
__device__ __align__(16) unsigned g_enc[B * WP];   // packed enc (1 -> +1, 0 -> -1)

// ================= kernel 1: pack sign bits, MLP-8 batched loads; quantize x ====================
// Warp task = 1024 consecutive floats of one row (= 32 packed words, 8 coalesced LDG.128/lane).
#define NROWS (S + L)                        // 717
#define RPR   10                             // regions of 1024 floats per row (10*1024 >= 10000)
#define PREP_WARPS  (NROWS * RPR)            // 7170
#define PREP_XWARPS 617                      // B*S / 32 = 19744/32
#define PREP_TWARPS (PREP_WARPS + PREP_XWARPS)
#define PREP_BLOCKS ((PREP_TWARPS + 7) / 8)  // 974 blocks x 256 thr

__global__ __launch_bounds__(256) void prep_kernel(const float* __restrict__ x,
                                                   const float* __restrict__ idw,
                                                   const float* __restrict__ lvw) {
    const int lane = threadIdx.x & 31;
    const int gw   = blockIdx.x * 8 + (threadIdx.x >> 5);

    if (gw < PREP_WARPS) {
        const int r      = gw / RPR;
        const int region = gw - r * RPR;
        const float* src = (r < S) ? (idw + (size_t)r * D) : (lvw + (size_t)(r - S) * D);
        unsigned*    dst = (r < S) ? (g_idp + r * WP)       : (g_lvp + (r - S) * WP);

        const int qbase = region * 256;                 // quad (float4) index base

        // 8 independent coalesced LDG.128, front-batched (MLP=8)
        float4 v[8];
        #pragma unroll
        for (int k = 0; k < 8; k++) {
            int q = qbase + k * 32 + lane;
            if (q < D / 4) v[k] = *reinterpret_cast<const float4*>(src + 4 * q);
            else           v[k] = make_float4(0.f, 0.f, 0.f, 0.f);   // sign bit -> 0
        }

        // 8 independent shfl pack trees: lane 8g ends holding word region*32 + 4k + g
        unsigned nib[8];
        #pragma unroll
        for (int k = 0; k < 8; k++) {
            unsigned n = (v[k].x > 0.f ? 1u : 0u) | (v[k].y > 0.f ? 2u : 0u)
                       | (v[k].z > 0.f ? 4u : 0u) | (v[k].w > 0.f ? 8u : 0u);
            n |= __shfl_down_sync(0xffffffffu, n, 1) << 4;
            n |= __shfl_down_sync(0xffffffffu, n, 2) << 8;
            n |= __shfl_down_sync(0xffffffffu, n, 4) << 16;
            nib[k] = n;
        }

        if ((lane & 7) == 0) {
            const int g = lane >> 3;
            #pragma unroll
            for (int k = 0; k < 8; k++) {
                int w = region * 32 + 4 * k + g;
                if (w < W) dst[w] = nib[k];
            }
        }
    } else {
        // quantize x -> level idx (rintf == round-half-even, matches jnp.round)
        int e = (gw - PREP_WARPS) * 32 + lane;          // exactly B*S = 19744 = 617*32
        if (e < B * S) {
            int qv = (int)rintf(x[e] * (float)(L - 1));
            g_idx[e] = min(max(qv, 0), L - 1);
        }
    }
}

// ================= 6-sample bitplane compressor (26 LOP3 per 6 samples) =========================
__device__ __forceinline__ void csa6(const unsigned xx[6], unsigned p[7]) {
    unsigned t01 = xx[0] ^ xx[1];
    unsigned l1  = t01 ^ xx[2];
    unsigned h1  = (xx[0] & xx[1]) | (xx[2] & t01);
    unsigned t34 = xx[3] ^ xx[4];
    unsigned l2  = t34 ^ xx[5];
    unsigned h2  = (xx[3] & xx[4]) | (xx[5] & t34);
    unsigned tl = l1 ^ l2;
    unsigned c0 = (l1 & l2) | (p[0] & tl);
    p[0] ^= tl;
    unsigned th  = h1 ^ h2;
    unsigned c1a = (h1 & h2) | (p[1] & th);
    unsigned s1  = p[1] ^ th;
    unsigned c1b = s1 & c0;
    p[1] = s1 ^ c0;
    unsigned tc = c1a ^ c1b;
    unsigned c2 = (c1a & c1b) | (p[2] & tc);
    p[2] ^= tc;
    unsigned t;
    t = p[3] & c2; p[3] ^= c2; c2 = t;
    t = p[4] & c2; p[4] ^= c2; c2 = t;
    t = p[5] & c2; p[5] ^= c2; c2 = t;
    p[6] ^= c2;
}

// ================= bit-sliced compare cnt < 309 (309 = 0b0100110101) ===========================
__device__ __forceinline__ unsigned cmp309(const unsigned A[10]) {
    unsigned lt = 0u, eq = 0xffffffffu;
    eq &= ~A[9];
    lt |= eq & ~A[8]; eq &= A[8];
    eq &= ~A[7];
    eq &= ~A[6];
    lt |= eq & ~A[5]; eq &= A[5];
    lt |= eq & ~A[4]; eq &= A[4];
    eq &= ~A[3];
    lt |= eq & ~A[2]; eq &= A[2];
    eq &= ~A[1];
    lt |= eq & ~A[0];
    return lt;
}

// ================= kernel 2 (fused): bind + count + merge + quantize -> g_enc ===================
__global__ __launch_bounds__(320) void main_kernel() {
    const int b  = blockIdx.x;
    const int wg = blockIdx.y;             // 0..9 word group
    const int sg = threadIdx.x >> 5;       // 0..9 sample group (warp)
    const int wl = threadIdx.x & 31;
    const int w  = wg * 32 + wl;           // word 0..319

    __shared__ int      sidx[S];
    __shared__ unsigned pl[7 * 320];

    for (int s = threadIdx.x; s < S; s += 320) sidx[s] = g_idx[b * S + s];
    __syncthreads();

    const int s0 = sg * 62;
    const int sn = (sg == 9) ? 59 : 62;    // 9*62 + 59 = 617

    unsigned p[7] = {0, 0, 0, 0, 0, 0, 0};

    const int full6 = sn / 6;              // 10 or 9
    for (int g = 0; g < full6; g++) {
        unsigned xx[6];
        #pragma unroll
        for (int k = 0; k < 6; k++) {
            int s = s0 + g * 6 + k;
            xx[k] = __ldg(&g_idp[s * WP + w]) ^ __ldg(&g_lvp[sidx[s] * WP + w]);
        }
        csa6(xx, p);
    }
    for (int s = s0 + full6 * 6; s < s0 + sn; s++) {   // remainder: 2 or 5 samples
        unsigned c = __ldg(&g_idp[s * WP + w]) ^ __ldg(&g_lvp[sidx[s] * WP + w]);
        #pragma unroll
        for (int k = 0; k < 7; k++) { unsigned t = p[k] & c; p[k] ^= c; c = t; }
    }

    #pragma unroll
    for (int k = 0; k < 7; k++) pl[k * 320 + threadIdx.x] = p[k];
    __syncthreads();

    if (threadIdx.x < 32) {
        unsigned A[10];
        #pragma unroll
        for (int k = 0; k < 10; k++) A[k] = 0u;
        #pragma unroll
        for (int g2 = 0; g2 < 10; g2++) {
            unsigned c = 0u;
            #pragma unroll
            for (int k = 0; k < 7; k++) {
                unsigned q = pl[k * 320 + g2 * 32 + wl];
                unsigned s2 = A[k] ^ q ^ c;
                c = (A[k] & q) | (c & (A[k] ^ q));
                A[k] = s2;
            }
            #pragma unroll
            for (int k = 7; k < 10; k++) { unsigned t = A[k] & c; A[k] ^= c; c = t; }
        }
        g_enc[b * WP + wg * 32 + wl] = cmp309(A);
    }
}

// ================= kernel 3: logits = enc(+/-1) . classify^T ===================================
__global__ __launch_bounds__(320) void logits_kernel(const float* __restrict__ cw,
                                                     float* __restrict__ out) {
    const int c    = blockIdx.x;
    const int b0   = blockIdx.y * 4;
    const int tid  = threadIdx.x;
    const int lane = tid & 31;
    const int wrp  = tid >> 5;            // 0..9
    const int sh   = 31 - lane;

    __shared__ uint4 se4[WP];
    {
        uint4 v;
        v.x = g_enc[(b0 + 0) * WP + tid];
        v.y = g_enc[(b0 + 1) * WP + tid];
        v.z = g_enc[(b0 + 2) * WP + tid];
        v.w = g_enc[(b0 + 3) * WP + tid];
        se4[tid] = v;
    }
    __syncthreads();

    const float* cwc = cw + (size_t)c * D;
    const unsigned MSB = 0x80000000u;

    float a0 = 0.0f, a1 = 0.0f, a2 = 0.0f, a3 = 0.0f;

    #pragma unroll
    for (int k = 0; k < 31; k++) {
        int d = k * 320 + tid;                       // max 9919 < D, no guard
        unsigned cb = __float_as_uint(__ldg(cwc + d));
        uint4 e = se4[k * 10 + wrp];                 // uniform per warp -> broadcast
        a0 += __uint_as_float(cb ^ (~(e.x << sh) & MSB));
        a1 += __uint_as_float(cb ^ (~(e.y << sh) & MSB));
        a2 += __uint_as_float(cb ^ (~(e.z << sh) & MSB));
        a3 += __uint_as_float(cb ^ (~(e.w << sh) & MSB));
    }
    if (tid < 80) {                                  // tail: d = 9920..9999
        int d = 9920 + tid;
        unsigned cb = __float_as_uint(__ldg(cwc + d));
        uint4 e = se4[310 + wrp];
        a0 += __uint_as_float(cb ^ (~(e.x << sh) & MSB));
        a1 += __uint_as_float(cb ^ (~(e.y << sh) & MSB));
        a2 += __uint_as_float(cb ^ (~(e.z << sh) & MSB));
        a3 += __uint_as_float(cb ^ (~(e.w << sh) & MSB));
    }

    __shared__ float red[10][4];
    float a[4] = {a0, a1, a2, a3};
    #pragma unroll
    for (int i = 0; i < 4; i++) {
        float v = a[i];
        #pragma unroll
        for (int o = 16; o > 0; o >>= 1) v += __shfl_down_sync(0xffffffffu, v, o);
        if (lane == 0) red[wrp][i] = v;
    }
    __syncthreads();
    if (tid < 4) {
        float v = 0.0f;
        #pragma unroll
        for (int k = 0; k < 10; k++) v += red[k][tid];
        out[(b0 + tid) * C + c] = v;
    }
}

// ================= launch =======================================================================
extern "C" void kernel_launch(void* const* d_in, const int* in_sizes, int n_in,
                              void* d_out, int out_size) {
    (void)in_sizes; (void)n_in; (void)out_size;
    const float* x   = (const float*)d_in[0];
    const float* idw = (const float*)d_in[1];
    const float* lvw = (const float*)d_in[2];
    const float* cw  = (const float*)d_in[3];
    float* out = (float*)d_out;

    prep_kernel<<<PREP_BLOCKS, 256>>>(x, idw, lvw);
    main_kernel<<<dim3(B, 10), 320>>>();
    logits_kernel<<<dim3(C, B / 4), 320>>>(cw, out);
}